// round 12
// baseline (speedup 1.0000x reference)
#include <cuda_runtime.h>
#include <cuda_fp16.h>

#define IN_F   128
#define HEADS  8
#define HC     16   // HEADS * OUT_C
#define NMAX   100000
#define NT     256   // threads (=nodes) per CTA in node_kernel
#define KT     32    // k-tile width
#define XPAD   36    // padded row stride (floats)

// Static scratch (no allocations allowed)
__device__ __align__(128) __half2 g_hh[NMAX * 8];     // h in fp16: 32B per node row
__device__ __align__(128) float g_asrc[NMAX * HEADS]; // 32B per node row
__device__ __align__(128) float g_adst[NMAX * HEADS]; // 32B per node row
__device__ __align__(16)  float g_acc[NMAX * 24];     // per node: S[16] then Z[8]

typedef unsigned long long u64;

// packed fp32x2 FMA: d = a*b + d (full fp32 precision, 2 FMAs per issue)
__device__ __forceinline__ void ffma2(u64& d, u64 a, u64 b) {
    asm("fma.rn.f32x2 %0, %1, %2, %3;" : "=l"(d) : "l"(a), "l"(b), "l"(d));
}
__device__ __forceinline__ u64 pack2(float lo, float hi) {
    u64 r;
    asm("mov.b64 %0, {%1, %2};" : "=l"(r) : "f"(lo), "f"(hi));
    return r;
}
__device__ __forceinline__ float2 unpack2(u64 v) {
    float lo, hi;
    asm("mov.b64 {%0, %1}, %2;" : "=f"(lo), "=f"(hi) : "l"(v));
    return make_float2(lo, hi);
}

// FFMA-only exp: exp(x) = 2^(x*log2e). |x| small here, rel err ~2e-6.
__device__ __forceinline__ float fexp(float x) {
    float y = x * 1.44269504f;
    float r = rintf(y);
    float f = y - r;
    float p = 1.3333558e-3f;
    p = fmaf(p, f, 9.6181291e-3f);
    p = fmaf(p, f, 5.5504109e-2f);
    p = fmaf(p, f, 2.4022651e-1f);
    p = fmaf(p, f, 6.9314718e-1f);
    p = fmaf(p, f, 1.0f);
    return __int_as_float(__float_as_int(p) + ((int)r << 23));
}

__device__ __forceinline__ float leaky(float l) {
    return fmaxf(l, 0.f) + 0.2f * fminf(l, 0.f);
}

// -------- Kernel 1: per-node transform via packed FFMA2 --------
// Thread per node. W (8KB) in smem read as ulonglong2 (LDS.128 -> two f32x2
// operands free). x staged in 32-col tiles; per k: 1 pack + 8 FFMA2.
__global__ __launch_bounds__(NT) void node_kernel(const float* __restrict__ x,
                                                  const float* __restrict__ W,
                                                  const float* __restrict__ att_src,
                                                  const float* __restrict__ att_dst,
                                                  int N) {
    __shared__ __align__(16) float Ws[IN_F * HC];   // 8KB
    __shared__ __align__(16) float xs[NT * XPAD];   // 36.9KB
    __shared__ float s_att[2 * HC];

    int tid = threadIdx.x;
    int n0 = blockIdx.x * NT;
    int n = n0 + tid;

    {
        const float4* Wg = (const float4*)W;
        float4* Wsv = (float4*)Ws;
        for (int i = tid; i < IN_F * HC / 4; i += NT) Wsv[i] = Wg[i];
    }
    if (tid < HC) { s_att[tid] = att_src[tid]; s_att[HC + tid] = att_dst[tid]; }

    u64 acc2[8];
#pragma unroll
    for (int j = 0; j < 8; j++) acc2[j] = 0ull;

    int valid = min(NT, N - n0);

#pragma unroll 1
    for (int kt = 0; kt < IN_F / KT; kt++) {
        __syncthreads();
        // Stage x[:, kt*32 .. +31] for NT rows: 2048 float4, 8 per thread.
#pragma unroll
        for (int q = 0; q < KT / 4; q++) {
            int idx = q * NT + tid;
            int r = idx >> 3, c = idx & 7;
            if (r < valid) {
                float4 v = *(const float4*)(x + (size_t)(n0 + r) * IN_F + kt * KT + c * 4);
                *(float4*)&xs[r * XPAD + c * 4] = v;
            }
        }
        __syncthreads();
        if (n < N) {
#pragma unroll
            for (int q = 0; q < KT / 4; q++) {
                float4 xv = *(const float4*)&xs[tid * XPAD + 4 * q];
                int kb = kt * KT + 4 * q;
#pragma unroll
                for (int kk = 0; kk < 4; kk++) {
                    float xk = (kk == 0) ? xv.x : (kk == 1) ? xv.y : (kk == 2) ? xv.z : xv.w;
                    u64 xk2 = pack2(xk, xk);
                    const ulonglong2* wr = (const ulonglong2*)&Ws[(kb + kk) * HC];
                    ulonglong2 wA = wr[0];   // j 0..3
                    ulonglong2 wB = wr[1];   // j 4..7
                    ulonglong2 wC = wr[2];   // j 8..11
                    ulonglong2 wD = wr[3];   // j 12..15
                    ffma2(acc2[0], xk2, wA.x);
                    ffma2(acc2[1], xk2, wA.y);
                    ffma2(acc2[2], xk2, wB.x);
                    ffma2(acc2[3], xk2, wB.y);
                    ffma2(acc2[4], xk2, wC.x);
                    ffma2(acc2[5], xk2, wC.y);
                    ffma2(acc2[6], xk2, wD.x);
                    ffma2(acc2[7], xk2, wD.y);
                }
            }
        }
    }

    if (n >= N) return;

    float acc[HC];
#pragma unroll
    for (int j = 0; j < 8; j++) {
        float2 v = unpack2(acc2[j]);
        acc[2 * j] = v.x;
        acc[2 * j + 1] = v.y;
    }

    // h in fp16 (32B row)
    {
        uint4 u0, u1;
        __half2 t;
        t = __floats2half2_rn(acc[0],  acc[1]);  u0.x = *(unsigned*)&t;
        t = __floats2half2_rn(acc[2],  acc[3]);  u0.y = *(unsigned*)&t;
        t = __floats2half2_rn(acc[4],  acc[5]);  u0.z = *(unsigned*)&t;
        t = __floats2half2_rn(acc[6],  acc[7]);  u0.w = *(unsigned*)&t;
        t = __floats2half2_rn(acc[8],  acc[9]);  u1.x = *(unsigned*)&t;
        t = __floats2half2_rn(acc[10], acc[11]); u1.y = *(unsigned*)&t;
        t = __floats2half2_rn(acc[12], acc[13]); u1.z = *(unsigned*)&t;
        t = __floats2half2_rn(acc[14], acc[15]); u1.w = *(unsigned*)&t;
        *(uint4*)(g_hh + (size_t)n * 8)     = u0;
        *(uint4*)(g_hh + (size_t)n * 8 + 4) = u1;
    }

    float as[HEADS], ad[HEADS];
#pragma unroll
    for (int hh = 0; hh < HEADS; hh++) {
        as[hh] = acc[2 * hh] * s_att[2 * hh] + acc[2 * hh + 1] * s_att[2 * hh + 1];
        ad[hh] = acc[2 * hh] * s_att[HC + 2 * hh] + acc[2 * hh + 1] * s_att[HC + 2 * hh + 1];
    }
    *(float4*)(g_asrc + (size_t)n * HEADS)     = make_float4(as[0], as[1], as[2], as[3]);
    *(float4*)(g_asrc + (size_t)n * HEADS + 4) = make_float4(as[4], as[5], as[6], as[7]);
    *(float4*)(g_adst + (size_t)n * HEADS)     = make_float4(ad[0], ad[1], ad[2], ad[3]);
    *(float4*)(g_adst + (size_t)n * HEADS + 4) = make_float4(ad[4], ad[5], ad[6], ad[7]);

    float p[HEADS];
#pragma unroll
    for (int hh = 0; hh < HEADS; hh++) p[hh] = fexp(leaky(as[hh] + ad[hh]));

    float* accp = g_acc + (size_t)n * 24;
#pragma unroll
    for (int q = 0; q < 4; q++) {
        *(float4*)(accp + 4 * q) = make_float4(p[2 * q] * acc[4 * q],
                                               p[2 * q] * acc[4 * q + 1],
                                               p[2 * q + 1] * acc[4 * q + 2],
                                               p[2 * q + 1] * acc[4 * q + 3]);
    }
    *(float4*)(accp + 16) = make_float4(p[0], p[1], p[2], p[3]);
    *(float4*)(accp + 20) = make_float4(p[4], p[5], p[6], p[7]);
}

// -------- Kernel 2: per-edge gather + fast-exp + scatter (vector red) --------
// Four threads per edge: thread q in {0..3} handles heads 2q, 2q+1.
__global__ __launch_bounds__(256) void edge_kernel(const int* __restrict__ ei, int E) {
    int t = blockIdx.x * blockDim.x + threadIdx.x;
    int e = t >> 2;
    if (e >= E) return;
    int q = t & 3;
    int s = __ldg(&ei[e]);
    int d = __ldg(&ei[E + e]);

    float2 a = *(const float2*)(g_asrc + (size_t)s * HEADS + 2 * q);
    float2 b = *(const float2*)(g_adst + (size_t)d * HEADS + 2 * q);
    float p0 = fexp(leaky(a.x + b.x));
    float p1 = fexp(leaky(a.y + b.y));

    uint2 hraw = *(const uint2*)(g_hh + (size_t)s * 8 + 2 * q);
    float2 f01 = __half22float2(*(__half2*)&hraw.x);
    float2 f23 = __half22float2(*(__half2*)&hraw.y);

    float* accp = g_acc + (size_t)d * 24;
    asm volatile("red.global.add.v4.f32 [%0], {%1, %2, %3, %4};"
                 :: "l"(accp + 4 * q),
                    "f"(p0 * f01.x), "f"(p0 * f01.y),
                    "f"(p1 * f23.x), "f"(p1 * f23.y) : "memory");

    float pp0 = __shfl_xor_sync(0xffffffffu, p0, 1);
    float pp1 = __shfl_xor_sync(0xffffffffu, p1, 1);
    if ((q & 1) == 0) {
        asm volatile("red.global.add.v4.f32 [%0], {%1, %2, %3, %4};"
                     :: "l"(accp + 16 + 2 * q),
                        "f"(p0), "f"(p1), "f"(pp0), "f"(pp1) : "memory");
    }
}

// -------- Kernel 3: normalize + bias + FC --------
__global__ __launch_bounds__(256) void out_kernel(const float* __restrict__ bias_gat,
                                                  const float* __restrict__ W_fc,
                                                  const float* __restrict__ b_fc,
                                                  float* __restrict__ out, int N) {
    int n = blockIdx.x * blockDim.x + threadIdx.x;
    if (n >= N) return;
    const float4* ap = (const float4*)(g_acc + (size_t)n * 24);
    float4 s0 = ap[0], s1 = ap[1], s2 = ap[2], s3 = ap[3];
    float4 z0 = ap[4], z1 = ap[5];
    float S[16] = { s0.x, s0.y, s0.z, s0.w, s1.x, s1.y, s1.z, s1.w,
                    s2.x, s2.y, s2.z, s2.w, s3.x, s3.y, s3.z, s3.w };
    float Z[8]  = { z0.x, z0.y, z0.z, z0.w, z1.x, z1.y, z1.z, z1.w };

    float o0 = __ldg(&b_fc[0]), o1 = __ldg(&b_fc[1]);
#pragma unroll
    for (int hh = 0; hh < 8; hh++) {
        float inv = 1.f / Z[hh];   // Z >= exp(self-loop) > 0 always
        float g0 = S[2 * hh] * inv + __ldg(&bias_gat[2 * hh]);
        float g1 = S[2 * hh + 1] * inv + __ldg(&bias_gat[2 * hh + 1]);
        o0 += g0 * __ldg(&W_fc[(2 * hh) * 2 + 0]) + g1 * __ldg(&W_fc[(2 * hh + 1) * 2 + 0]);
        o1 += g0 * __ldg(&W_fc[(2 * hh) * 2 + 1]) + g1 * __ldg(&W_fc[(2 * hh + 1) * 2 + 1]);
    }
    ((float2*)out)[n] = make_float2(o0, o1);
}

extern "C" void kernel_launch(void* const* d_in, const int* in_sizes, int n_in,
                              void* d_out, int out_size) {
    const float* x        = (const float*)d_in[0];
    const int*   ei       = (const int*)d_in[1];   // int32 (JAX x64 disabled)
    // d_in[2] = edge_attr: unused (GATConv built without edge_dim)
    const float* W        = (const float*)d_in[3];
    const float* att_src  = (const float*)d_in[4];
    const float* att_dst  = (const float*)d_in[5];
    const float* bias_gat = (const float*)d_in[6];
    const float* W_fc     = (const float*)d_in[7];
    const float* b_fc     = (const float*)d_in[8];

    int N = in_sizes[0] / IN_F;
    int E = in_sizes[1] / 2;

    node_kernel<<<(N + NT - 1) / NT, NT>>>(x, W, att_src, att_dst, N);
    long long tthreads = 4LL * E;
    edge_kernel<<<(int)((tthreads + 255) / 256), 256>>>(ei, E);
    out_kernel<<<(N + 255) / 256, 256>>>(bias_gat, W_fc, b_fc, (float*)d_out, N);
}

// round 13
// speedup vs baseline: 1.1290x; 1.1290x over previous
#include <cuda_runtime.h>
#include <cuda_fp16.h>

#define IN_F   128
#define HEADS  8
#define HC     16   // HEADS * OUT_C
#define NMAX   100000
#define NT     128   // threads (=nodes) per CTA in node_kernel
#define KT     32    // k-tile width
#define XPAD   36    // padded row stride (floats)

// Static scratch (no allocations allowed)
// g_pack[n] = 64B: 4 q-blocks {asrc[2q], asrc[2q+1] fp32, h[4q..4q+3] fp16}
__device__ __align__(128) uint4 g_pack[NMAX * 4];
__device__ __align__(128) float g_adst[NMAX * HEADS]; // 32B per node row
__device__ __align__(16)  float g_acc[NMAX * 24];     // per node: S[16] then Z[8]

// FFMA-only exp: exp(x) = 2^(x*log2e). |x| small here, rel err ~2e-6.
__device__ __forceinline__ float fexp(float x) {
    float y = x * 1.44269504f;
    float r = rintf(y);
    float f = y - r;
    float p = 1.3333558e-3f;
    p = fmaf(p, f, 9.6181291e-3f);
    p = fmaf(p, f, 5.5504109e-2f);
    p = fmaf(p, f, 2.4022651e-1f);
    p = fmaf(p, f, 6.9314718e-1f);
    p = fmaf(p, f, 1.0f);
    return __int_as_float(__float_as_int(p) + ((int)r << 23));
}

__device__ __forceinline__ float leaky(float l) {
    return fmaxf(l, 0.f) + 0.2f * fminf(l, 0.f);
}

// -------- Kernel 1: per-node transform + self-loop init (R10 structure) --------
__global__ __launch_bounds__(NT, 4) void node_kernel(const float* __restrict__ x,
                                                     const float* __restrict__ W,
                                                     const float* __restrict__ att_src,
                                                     const float* __restrict__ att_dst,
                                                     int N) {
    __shared__ __align__(16) float Ws[IN_F * HC];   // 8KB
    __shared__ __align__(16) float xs[NT * XPAD];   // 18.4KB
    __shared__ float s_att[2 * HC];

    int tid = threadIdx.x;
    int n0 = blockIdx.x * NT;
    int n = n0 + tid;

    {
        const float4* Wg = (const float4*)W;
        float4* Wsv = (float4*)Ws;
        for (int i = tid; i < IN_F * HC / 4; i += NT) Wsv[i] = Wg[i];
    }
    if (tid < HC) { s_att[tid] = att_src[tid]; s_att[HC + tid] = att_dst[tid]; }

    int valid = min(NT, N - n0);
    float4 stage[8];
    {
#pragma unroll
        for (int q = 0; q < 8; q++) {
            int idx = q * NT + tid;
            int r = idx >> 3, c = idx & 7;
            if (r < valid)
                stage[q] = *(const float4*)(x + (size_t)(n0 + r) * IN_F + c * 4);
        }
    }

    float acc[HC];
#pragma unroll
    for (int j = 0; j < HC; j++) acc[j] = 0.f;

#pragma unroll 1
    for (int kt = 0; kt < IN_F / KT; kt++) {
        __syncthreads();
        {
#pragma unroll
            for (int q = 0; q < 8; q++) {
                int idx = q * NT + tid;
                int r = idx >> 3, c = idx & 7;
                if (r < valid) *(float4*)&xs[r * XPAD + c * 4] = stage[q];
            }
        }
        __syncthreads();
        if (kt < IN_F / KT - 1) {
#pragma unroll
            for (int q = 0; q < 8; q++) {
                int idx = q * NT + tid;
                int r = idx >> 3, c = idx & 7;
                if (r < valid)
                    stage[q] = *(const float4*)(x + (size_t)(n0 + r) * IN_F + (kt + 1) * KT + c * 4);
            }
        }
        if (n < N) {
#pragma unroll
            for (int q = 0; q < KT / 4; q++) {
                float4 xv = *(const float4*)&xs[tid * XPAD + 4 * q];
                int kb = kt * KT + 4 * q;
                const float4* wr = (const float4*)&Ws[kb * HC];
#pragma unroll
                for (int kk = 0; kk < 4; kk++) {
                    float xk = (kk == 0) ? xv.x : (kk == 1) ? xv.y : (kk == 2) ? xv.z : xv.w;
                    float4 w0 = wr[kk * 4 + 0];
                    float4 w1 = wr[kk * 4 + 1];
                    float4 w2 = wr[kk * 4 + 2];
                    float4 w3 = wr[kk * 4 + 3];
                    acc[0]  = fmaf(xk, w0.x, acc[0]);
                    acc[1]  = fmaf(xk, w0.y, acc[1]);
                    acc[2]  = fmaf(xk, w0.z, acc[2]);
                    acc[3]  = fmaf(xk, w0.w, acc[3]);
                    acc[4]  = fmaf(xk, w1.x, acc[4]);
                    acc[5]  = fmaf(xk, w1.y, acc[5]);
                    acc[6]  = fmaf(xk, w1.z, acc[6]);
                    acc[7]  = fmaf(xk, w1.w, acc[7]);
                    acc[8]  = fmaf(xk, w2.x, acc[8]);
                    acc[9]  = fmaf(xk, w2.y, acc[9]);
                    acc[10] = fmaf(xk, w2.z, acc[10]);
                    acc[11] = fmaf(xk, w2.w, acc[11]);
                    acc[12] = fmaf(xk, w3.x, acc[12]);
                    acc[13] = fmaf(xk, w3.y, acc[13]);
                    acc[14] = fmaf(xk, w3.z, acc[14]);
                    acc[15] = fmaf(xk, w3.w, acc[15]);
                }
            }
        }
    }

    if (n >= N) return;

    float as[HEADS], ad[HEADS];
#pragma unroll
    for (int hh = 0; hh < HEADS; hh++) {
        as[hh] = acc[2 * hh] * s_att[2 * hh] + acc[2 * hh + 1] * s_att[2 * hh + 1];
        ad[hh] = acc[2 * hh] * s_att[HC + 2 * hh] + acc[2 * hh + 1] * s_att[HC + 2 * hh + 1];
    }

    // packed src struct: per q-block {asrc[2q], asrc[2q+1], h[4q..4q+3] fp16}
#pragma unroll
    for (int q = 0; q < 4; q++) {
        uint4 pk;
        pk.x = __float_as_uint(as[2 * q]);
        pk.y = __float_as_uint(as[2 * q + 1]);
        __half2 t0 = __floats2half2_rn(acc[4 * q],     acc[4 * q + 1]);
        __half2 t1 = __floats2half2_rn(acc[4 * q + 2], acc[4 * q + 3]);
        pk.z = *(unsigned*)&t0;
        pk.w = *(unsigned*)&t1;
        g_pack[(size_t)n * 4 + q] = pk;
    }

    *(float4*)(g_adst + (size_t)n * HEADS)     = make_float4(ad[0], ad[1], ad[2], ad[3]);
    *(float4*)(g_adst + (size_t)n * HEADS + 4) = make_float4(ad[4], ad[5], ad[6], ad[7]);

    float p[HEADS];
#pragma unroll
    for (int hh = 0; hh < HEADS; hh++) p[hh] = fexp(leaky(as[hh] + ad[hh]));

    float* accp = g_acc + (size_t)n * 24;
#pragma unroll
    for (int q = 0; q < 4; q++) {
        *(float4*)(accp + 4 * q) = make_float4(p[2 * q] * acc[4 * q],
                                               p[2 * q] * acc[4 * q + 1],
                                               p[2 * q + 1] * acc[4 * q + 2],
                                               p[2 * q + 1] * acc[4 * q + 3]);
    }
    *(float4*)(accp + 16) = make_float4(p[0], p[1], p[2], p[3]);
    *(float4*)(accp + 20) = make_float4(p[4], p[5], p[6], p[7]);
}

// -------- Kernel 2: per-edge gather + fast-exp + scatter (vector red) --------
// Four threads per edge: thread q handles heads 2q, 2q+1. One 16B src gather.
__global__ __launch_bounds__(256) void edge_kernel(const int* __restrict__ ei, int E) {
    int t = blockIdx.x * blockDim.x + threadIdx.x;
    int e = t >> 2;
    if (e >= E) return;
    int q = t & 3;
    int s = __ldg(&ei[e]);
    int d = __ldg(&ei[E + e]);

    uint4 pk = *(const uint4*)(g_pack + (size_t)s * 4 + q);   // 1 sector
    float2 b = *(const float2*)(g_adst + (size_t)d * HEADS + 2 * q);  // 1 sector
    float p0 = fexp(leaky(__uint_as_float(pk.x) + b.x));
    float p1 = fexp(leaky(__uint_as_float(pk.y) + b.y));
    float2 f01 = __half22float2(*(__half2*)&pk.z);
    float2 f23 = __half22float2(*(__half2*)&pk.w);

    float* accp = g_acc + (size_t)d * 24;
    asm volatile("red.global.add.v4.f32 [%0], {%1, %2, %3, %4};"
                 :: "l"(accp + 4 * q),
                    "f"(p0 * f01.x), "f"(p0 * f01.y),
                    "f"(p1 * f23.x), "f"(p1 * f23.y) : "memory");

    float pp0 = __shfl_xor_sync(0xffffffffu, p0, 1);
    float pp1 = __shfl_xor_sync(0xffffffffu, p1, 1);
    if ((q & 1) == 0) {
        asm volatile("red.global.add.v4.f32 [%0], {%1, %2, %3, %4};"
                     :: "l"(accp + 16 + 2 * q),
                        "f"(p0), "f"(p1), "f"(pp0), "f"(pp1) : "memory");
    }
}

// -------- Kernel 3: normalize + bias + FC --------
__global__ __launch_bounds__(256) void out_kernel(const float* __restrict__ bias_gat,
                                                  const float* __restrict__ W_fc,
                                                  const float* __restrict__ b_fc,
                                                  float* __restrict__ out, int N) {
    int n = blockIdx.x * blockDim.x + threadIdx.x;
    if (n >= N) return;
    const float4* ap = (const float4*)(g_acc + (size_t)n * 24);
    float4 s0 = ap[0], s1 = ap[1], s2 = ap[2], s3 = ap[3];
    float4 z0 = ap[4], z1 = ap[5];
    float S[16] = { s0.x, s0.y, s0.z, s0.w, s1.x, s1.y, s1.z, s1.w,
                    s2.x, s2.y, s2.z, s2.w, s3.x, s3.y, s3.z, s3.w };
    float Z[8]  = { z0.x, z0.y, z0.z, z0.w, z1.x, z1.y, z1.z, z1.w };

    float o0 = __ldg(&b_fc[0]), o1 = __ldg(&b_fc[1]);
#pragma unroll
    for (int hh = 0; hh < 8; hh++) {
        float inv = 1.f / Z[hh];   // Z >= exp(self-loop) > 0 always
        float g0 = S[2 * hh] * inv + __ldg(&bias_gat[2 * hh]);
        float g1 = S[2 * hh + 1] * inv + __ldg(&bias_gat[2 * hh + 1]);
        o0 += g0 * __ldg(&W_fc[(2 * hh) * 2 + 0]) + g1 * __ldg(&W_fc[(2 * hh + 1) * 2 + 0]);
        o1 += g0 * __ldg(&W_fc[(2 * hh) * 2 + 1]) + g1 * __ldg(&W_fc[(2 * hh + 1) * 2 + 1]);
    }
    ((float2*)out)[n] = make_float2(o0, o1);
}

extern "C" void kernel_launch(void* const* d_in, const int* in_sizes, int n_in,
                              void* d_out, int out_size) {
    const float* x        = (const float*)d_in[0];
    const int*   ei       = (const int*)d_in[1];   // int32 (JAX x64 disabled)
    // d_in[2] = edge_attr: unused (GATConv built without edge_dim)
    const float* W        = (const float*)d_in[3];
    const float* att_src  = (const float*)d_in[4];
    const float* att_dst  = (const float*)d_in[5];
    const float* bias_gat = (const float*)d_in[6];
    const float* W_fc     = (const float*)d_in[7];
    const float* b_fc     = (const float*)d_in[8];

    int N = in_sizes[0] / IN_F;
    int E = in_sizes[1] / 2;

    node_kernel<<<(N + NT - 1) / NT, NT>>>(x, W, att_src, att_dst, N);
    long long tthreads = 4LL * E;
    edge_kernel<<<(int)((tthreads + 255) / 256), 256>>>(ei, E);
    out_kernel<<<(N + 255) / 256, 256>>>(bias_gat, W_fc, b_fc, (float*)d_out, N);
}

// round 14
// speedup vs baseline: 1.1495x; 1.0181x over previous
#include <cuda_runtime.h>
#include <cuda_fp16.h>

#define IN_F   128
#define HEADS  8
#define HC     16   // HEADS * OUT_C
#define NMAX   100000
#define NT     128   // threads (=nodes) per CTA in node_kernel
#define KT     32    // k-tile width
#define XPAD   36    // padded row stride (floats); 144B = 9*16B, cp.async-aligned
#define NTILES (IN_F / KT)

// Static scratch (no allocations allowed)
// g_pack[n] = 64B: 4 q-blocks {asrc[2q], asrc[2q+1] fp32, h[4q..4q+3] fp16}
__device__ __align__(128) uint4 g_pack[NMAX * 4];
__device__ __align__(128) float g_adst[NMAX * HEADS]; // 32B per node row
__device__ __align__(16)  float g_acc[NMAX * 24];     // per node: S[16] then Z[8]

// FFMA-only exp: exp(x) = 2^(x*log2e). |x| small here, rel err ~2e-6.
__device__ __forceinline__ float fexp(float x) {
    float y = x * 1.44269504f;
    float r = rintf(y);
    float f = y - r;
    float p = 1.3333558e-3f;
    p = fmaf(p, f, 9.6181291e-3f);
    p = fmaf(p, f, 5.5504109e-2f);
    p = fmaf(p, f, 2.4022651e-1f);
    p = fmaf(p, f, 6.9314718e-1f);
    p = fmaf(p, f, 1.0f);
    return __int_as_float(__float_as_int(p) + ((int)r << 23));
}

__device__ __forceinline__ float leaky(float l) {
    return fmaxf(l, 0.f) + 0.2f * fminf(l, 0.f);
}

__device__ __forceinline__ void cp16(unsigned dst, const void* src) {
    asm volatile("cp.async.ca.shared.global [%0], [%1], 16;" :: "r"(dst), "l"(src) : "memory");
}
__device__ __forceinline__ void cp_commit() {
    asm volatile("cp.async.commit_group;" ::: "memory");
}
template <int NW>
__device__ __forceinline__ void cp_wait() {
    asm volatile("cp.async.wait_group %0;" :: "n"(NW) : "memory");
}

// -------- Kernel 1: per-node transform, cp.async double-buffered staging --------
__global__ __launch_bounds__(NT, 5) void node_kernel(const float* __restrict__ x,
                                                     const float* __restrict__ W,
                                                     const float* __restrict__ att_src,
                                                     const float* __restrict__ att_dst,
                                                     int N) {
    __shared__ __align__(16) float Ws[IN_F * HC];      // 8KB
    __shared__ __align__(16) float xs[2][NT * XPAD];   // 2 x 18.4KB
    __shared__ float s_att[2 * HC];

    int tid = threadIdx.x;
    int n0 = blockIdx.x * NT;
    int n = n0 + tid;
    int valid = min(NT, N - n0);

    // Per-thread staging slots: idx = q*NT+tid -> row r=idx>>3, col c=idx&7
    int rr[8], cc[8];
#pragma unroll
    for (int q = 0; q < 8; q++) {
        int idx = q * NT + tid;
        rr[q] = idx >> 3;
        cc[q] = idx & 7;
    }

    // Prologue: kick off tile 0 immediately (DRAM latency overlaps W load)
#pragma unroll
    for (int q = 0; q < 8; q++) {
        if (rr[q] < valid)
            cp16((unsigned)__cvta_generic_to_shared(&xs[0][rr[q] * XPAD + cc[q] * 4]),
                 x + (size_t)(n0 + rr[q]) * IN_F + cc[q] * 4);
    }
    cp_commit();

    {
        const float4* Wg = (const float4*)W;
        float4* Wsv = (float4*)Ws;
        for (int i = tid; i < IN_F * HC / 4; i += NT) Wsv[i] = Wg[i];
    }
    if (tid < HC) { s_att[tid] = att_src[tid]; s_att[HC + tid] = att_dst[tid]; }

    float acc[HC];
#pragma unroll
    for (int j = 0; j < HC; j++) acc[j] = 0.f;

#pragma unroll
    for (int kt = 0; kt < NTILES; kt++) {
        // Issue next tile into the other buffer
        if (kt + 1 < NTILES) {
#pragma unroll
            for (int q = 0; q < 8; q++) {
                if (rr[q] < valid)
                    cp16((unsigned)__cvta_generic_to_shared(&xs[(kt + 1) & 1][rr[q] * XPAD + cc[q] * 4]),
                         x + (size_t)(n0 + rr[q]) * IN_F + (kt + 1) * KT + cc[q] * 4);
            }
            cp_commit();
            cp_wait<1>();   // current tile (kt) complete; kt+1 may be in flight
        } else {
            cp_wait<0>();
        }
        __syncthreads();

        if (n < N) {
            const float* xr = &xs[kt & 1][tid * XPAD];
#pragma unroll
            for (int q = 0; q < KT / 4; q++) {
                float4 xv = *(const float4*)&xr[4 * q];
                int kb = kt * KT + 4 * q;
                const float4* wr = (const float4*)&Ws[kb * HC];
#pragma unroll
                for (int kk = 0; kk < 4; kk++) {
                    float xk = (kk == 0) ? xv.x : (kk == 1) ? xv.y : (kk == 2) ? xv.z : xv.w;
                    float4 w0 = wr[kk * 4 + 0];
                    float4 w1 = wr[kk * 4 + 1];
                    float4 w2 = wr[kk * 4 + 2];
                    float4 w3 = wr[kk * 4 + 3];
                    acc[0]  = fmaf(xk, w0.x, acc[0]);
                    acc[1]  = fmaf(xk, w0.y, acc[1]);
                    acc[2]  = fmaf(xk, w0.z, acc[2]);
                    acc[3]  = fmaf(xk, w0.w, acc[3]);
                    acc[4]  = fmaf(xk, w1.x, acc[4]);
                    acc[5]  = fmaf(xk, w1.y, acc[5]);
                    acc[6]  = fmaf(xk, w1.z, acc[6]);
                    acc[7]  = fmaf(xk, w1.w, acc[7]);
                    acc[8]  = fmaf(xk, w2.x, acc[8]);
                    acc[9]  = fmaf(xk, w2.y, acc[9]);
                    acc[10] = fmaf(xk, w2.z, acc[10]);
                    acc[11] = fmaf(xk, w2.w, acc[11]);
                    acc[12] = fmaf(xk, w3.x, acc[12]);
                    acc[13] = fmaf(xk, w3.y, acc[13]);
                    acc[14] = fmaf(xk, w3.z, acc[14]);
                    acc[15] = fmaf(xk, w3.w, acc[15]);
                }
            }
        }
        __syncthreads();   // all readers done before this buffer is re-filled
    }

    if (n >= N) return;

    float as[HEADS], ad[HEADS];
#pragma unroll
    for (int hh = 0; hh < HEADS; hh++) {
        as[hh] = acc[2 * hh] * s_att[2 * hh] + acc[2 * hh + 1] * s_att[2 * hh + 1];
        ad[hh] = acc[2 * hh] * s_att[HC + 2 * hh] + acc[2 * hh + 1] * s_att[HC + 2 * hh + 1];
    }

    // packed src struct: per q-block {asrc[2q], asrc[2q+1], h[4q..4q+3] fp16}
#pragma unroll
    for (int q = 0; q < 4; q++) {
        uint4 pk;
        pk.x = __float_as_uint(as[2 * q]);
        pk.y = __float_as_uint(as[2 * q + 1]);
        __half2 t0 = __floats2half2_rn(acc[4 * q],     acc[4 * q + 1]);
        __half2 t1 = __floats2half2_rn(acc[4 * q + 2], acc[4 * q + 3]);
        pk.z = *(unsigned*)&t0;
        pk.w = *(unsigned*)&t1;
        g_pack[(size_t)n * 4 + q] = pk;
    }

    *(float4*)(g_adst + (size_t)n * HEADS)     = make_float4(ad[0], ad[1], ad[2], ad[3]);
    *(float4*)(g_adst + (size_t)n * HEADS + 4) = make_float4(ad[4], ad[5], ad[6], ad[7]);

    float p[HEADS];
#pragma unroll
    for (int hh = 0; hh < HEADS; hh++) p[hh] = fexp(leaky(as[hh] + ad[hh]));

    float* accp = g_acc + (size_t)n * 24;
#pragma unroll
    for (int q = 0; q < 4; q++) {
        *(float4*)(accp + 4 * q) = make_float4(p[2 * q] * acc[4 * q],
                                               p[2 * q] * acc[4 * q + 1],
                                               p[2 * q + 1] * acc[4 * q + 2],
                                               p[2 * q + 1] * acc[4 * q + 3]);
    }
    *(float4*)(accp + 16) = make_float4(p[0], p[1], p[2], p[3]);
    *(float4*)(accp + 20) = make_float4(p[4], p[5], p[6], p[7]);
}

// -------- Kernel 2: per-edge gather + fast-exp + scatter (vector red) --------
// Four threads per edge: thread q handles heads 2q, 2q+1. One 16B src gather.
__global__ __launch_bounds__(256) void edge_kernel(const int* __restrict__ ei, int E) {
    int t = blockIdx.x * blockDim.x + threadIdx.x;
    int e = t >> 2;
    if (e >= E) return;
    int q = t & 3;
    int s = __ldg(&ei[e]);
    int d = __ldg(&ei[E + e]);

    uint4 pk = *(const uint4*)(g_pack + (size_t)s * 4 + q);
    float2 b = *(const float2*)(g_adst + (size_t)d * HEADS + 2 * q);
    float p0 = fexp(leaky(__uint_as_float(pk.x) + b.x));
    float p1 = fexp(leaky(__uint_as_float(pk.y) + b.y));
    float2 f01 = __half22float2(*(__half2*)&pk.z);
    float2 f23 = __half22float2(*(__half2*)&pk.w);

    float* accp = g_acc + (size_t)d * 24;
    asm volatile("red.global.add.v4.f32 [%0], {%1, %2, %3, %4};"
                 :: "l"(accp + 4 * q),
                    "f"(p0 * f01.x), "f"(p0 * f01.y),
                    "f"(p1 * f23.x), "f"(p1 * f23.y) : "memory");

    float pp0 = __shfl_xor_sync(0xffffffffu, p0, 1);
    float pp1 = __shfl_xor_sync(0xffffffffu, p1, 1);
    if ((q & 1) == 0) {
        asm volatile("red.global.add.v4.f32 [%0], {%1, %2, %3, %4};"
                     :: "l"(accp + 16 + 2 * q),
                        "f"(p0), "f"(p1), "f"(pp0), "f"(pp1) : "memory");
    }
}

// -------- Kernel 3: normalize + bias + FC --------
__global__ __launch_bounds__(256) void out_kernel(const float* __restrict__ bias_gat,
                                                  const float* __restrict__ W_fc,
                                                  const float* __restrict__ b_fc,
                                                  float* __restrict__ out, int N) {
    int n = blockIdx.x * blockDim.x + threadIdx.x;
    if (n >= N) return;
    const float4* ap = (const float4*)(g_acc + (size_t)n * 24);
    float4 s0 = ap[0], s1 = ap[1], s2 = ap[2], s3 = ap[3];
    float4 z0 = ap[4], z1 = ap[5];
    float S[16] = { s0.x, s0.y, s0.z, s0.w, s1.x, s1.y, s1.z, s1.w,
                    s2.x, s2.y, s2.z, s2.w, s3.x, s3.y, s3.z, s3.w };
    float Z[8]  = { z0.x, z0.y, z0.z, z0.w, z1.x, z1.y, z1.z, z1.w };

    float o0 = __ldg(&b_fc[0]), o1 = __ldg(&b_fc[1]);
#pragma unroll
    for (int hh = 0; hh < 8; hh++) {
        float inv = 1.f / Z[hh];   // Z >= exp(self-loop) > 0 always
        float g0 = S[2 * hh] * inv + __ldg(&bias_gat[2 * hh]);
        float g1 = S[2 * hh + 1] * inv + __ldg(&bias_gat[2 * hh + 1]);
        o0 += g0 * __ldg(&W_fc[(2 * hh) * 2 + 0]) + g1 * __ldg(&W_fc[(2 * hh + 1) * 2 + 0]);
        o1 += g0 * __ldg(&W_fc[(2 * hh) * 2 + 1]) + g1 * __ldg(&W_fc[(2 * hh + 1) * 2 + 1]);
    }
    ((float2*)out)[n] = make_float2(o0, o1);
}

extern "C" void kernel_launch(void* const* d_in, const int* in_sizes, int n_in,
                              void* d_out, int out_size) {
    const float* x        = (const float*)d_in[0];
    const int*   ei       = (const int*)d_in[1];   // int32 (JAX x64 disabled)
    // d_in[2] = edge_attr: unused (GATConv built without edge_dim)
    const float* W        = (const float*)d_in[3];
    const float* att_src  = (const float*)d_in[4];
    const float* att_dst  = (const float*)d_in[5];
    const float* bias_gat = (const float*)d_in[6];
    const float* W_fc     = (const float*)d_in[7];
    const float* b_fc     = (const float*)d_in[8];

    int N = in_sizes[0] / IN_F;
    int E = in_sizes[1] / 2;

    node_kernel<<<(N + NT - 1) / NT, NT>>>(x, W, att_src, att_dst, N);
    long long tthreads = 4LL * E;
    edge_kernel<<<(int)((tthreads + 255) / 256), 256>>>(ei, E);
    out_kernel<<<(N + 255) / 256, 256>>>(bias_gat, W_fc, b_fc, (float*)d_out, N);
}